// round 15
// baseline (speedup 1.0000x reference)
#include <cuda_runtime.h>
#include <cuda_bf16.h>
#include <cstdint>

// ---------------- problem constants ----------------
#define BATCH 32
#define KSAMP 16
#define D_IN  312
#define H1    1024
#define H2    2048
#define D_OUT 128
#define ROWS  17
#define NPAD  24
#define INV_T 8.3333333333333333f
#define KCC   64            // K per chunk
#define SP    35            // smem u32 stride per A row (32 k-pairs + 3 pad)
#define KP0   160           // packed X pair-stride per row (L0: 5*64/2, padded past 312)
#define KP1   512
#define KP2   1024

// ---------------- scratch (no allocations allowed; referenced ONLY from device code) ----
__device__ float g_h1[(size_t)BATCH * ROWS * H1];            // 2.2 MB
__device__ float g_h2[(size_t)BATCH * ROWS * H2];            // 4.5 MB
__device__ float g_p [(size_t)4 * BATCH * ROWS * D_OUT];     // 1.1 MB (L3 split-K x4)
__device__ uint2 g_x0[(size_t)BATCH * NPAD * KP0];           // 1.0 MB packed bf16 hi/lo
__device__ uint2 g_x1[(size_t)BATCH * NPAD * KP1];           // 3.1 MB
__device__ uint2 g_x2[(size_t)BATCH * NPAD * KP2];           // 6.3 MB

// ---------------- bf16 hi/lo pair packing ----------------
__device__ __forceinline__ uint32_t hi_pair(float f0, float f1) {
    return __byte_perm(__float_as_uint(f0), __float_as_uint(f1), 0x7632);
}
__device__ __forceinline__ uint32_t lo_pair(float f0, float f1) {
    float l0 = f0 - __uint_as_float(__float_as_uint(f0) & 0xFFFF0000u);
    float l1 = f1 - __uint_as_float(__float_as_uint(f1) & 0xFFFF0000u);
    __nv_bfloat162 p = __floats2bfloat162_rn(l0, l1);
    return reinterpret_cast<uint32_t&>(p);
}

// ---------------- mma.sync m16n8k16 bf16 (HMMA, plain compute_103) ----------------
__device__ __forceinline__ void mma16816(float d[4], const uint32_t a[4], const uint32_t b[2]) {
    asm volatile(
        "mma.sync.aligned.m16n8k16.row.col.f32.bf16.bf16.f32 "
        "{%0,%1,%2,%3}, {%4,%5,%6,%7}, {%8,%9}, {%0,%1,%2,%3};"
        : "+f"(d[0]), "+f"(d[1]), "+f"(d[2]), "+f"(d[3])
        : "r"(a[0]), "r"(a[1]), "r"(a[2]), "r"(a[3]), "r"(b[0]), "r"(b[1]));
}

// ---------------- pack kernels: fp32 activations -> interleaved bf16 hi/lo pairs ----------------
__global__ void __launch_bounds__(256) pack_x0(const float* __restrict__ v2s,
                                               const int* __restrict__ sidx) {
    const int b = blockIdx.x;
    __shared__ int sRow[NPAD];
    if (threadIdx.x < NPAD)
        sRow[threadIdx.x] = (threadIdx.x == 0) ? b
                          : (threadIdx.x < ROWS ? sidx[b * KSAMP + threadIdx.x - 1] : -1);
    __syncthreads();
    for (int i = threadIdx.x; i < NPAD * KP0; i += 256) {
        const int n = i / KP0, p = i - n * KP0;
        const int r = sRow[n];
        float f0 = 0.f, f1 = 0.f;
        if (r >= 0 && 2 * p + 1 < D_IN) {
            f0 = v2s[(size_t)r * D_IN + 2 * p];
            f1 = v2s[(size_t)r * D_IN + 2 * p + 1];
        }
        g_x0[(size_t)b * NPAD * KP0 + i] = make_uint2(hi_pair(f0, f1), lo_pair(f0, f1));
    }
}

// LAYER 1: g_h1 -> g_x1 ; LAYER 2: g_h2 -> g_x2  (globals referenced in device code only)
template<int LAYER>
__global__ void __launch_bounds__(256) pack_h() {
    constexpr int H = (LAYER == 1) ? H1 : H2;
    const float* __restrict__ src = (LAYER == 1) ? g_h1 : g_h2;
    uint2* __restrict__ dst = (LAYER == 1) ? g_x1 : g_x2;
    const int bn = blockIdx.x;                 // b*NPAD + n
    const int b = bn / NPAD, n = bn - b * NPAD;
    const bool ok = (n < ROWS);
    const float2* __restrict__ s = reinterpret_cast<const float2*>(
        src + ((size_t)b * ROWS + (ok ? n : 0)) * H);
    uint2* __restrict__ d = dst + (size_t)bn * (H / 2);
    for (int p = threadIdx.x; p < H / 2; p += 256) {
        float2 f = ok ? s[p] : make_float2(0.f, 0.f);
        d[p] = make_uint2(hi_pair(f.x, f.y), lo_pair(f.x, f.y));
    }
}

// ---------------- GEMM kernel: 4 j-tiles (m32) x 2 k-halves across 8 warps ----------------
template<int LAYER>
__global__ void __launch_bounds__(256, 2) gemm_kernel(const int* __restrict__ tar,
                                                      const float* __restrict__ W,
                                                      const float* __restrict__ bias) {
    constexpr int LDW   = (LAYER == 0) ? H1 : (LAYER == 1) ? H2 : D_OUT;
    constexpr int KFULL = (LAYER == 0) ? D_IN : (LAYER == 1) ? H1 : H2;
    constexpr int KBLK  = (LAYER == 2) ? 512 : KFULL;
    constexpr int NCH   = (KBLK + KCC - 1) / KCC;            // 5 / 16 / 8
    constexpr int JB    = LDW / 128;
    constexpr int KP    = (LAYER == 0) ? KP0 : (LAYER == 1) ? KP1 : KP2;

    __shared__ uint32_t sAhi[128 * SP], sAlo[128 * SP];

    const int tid = threadIdx.x;
    int b, jb, kb;
    if (LAYER == 2) { b = blockIdx.x >> 2; kb = blockIdx.x & 3; jb = 0; }
    else            { b = blockIdx.x / JB; jb = blockIdx.x % JB; kb = 0; }
    const int e = tar[b];
    const int kbase = (LAYER == 2) ? kb * 512 : 0;
    const int j0 = jb * 128;

    const int w = tid >> 5, l = tid & 31;
    const int g = l >> 2, t = l & 3;
    const int jt = w & 3;                  // j-tile (m32)
    const int h  = w >> 2;                 // k-half (k32)
    const int jl = jt * 32 + l;            // A-fill column

    const float* __restrict__ wcol = W + (size_t)e * KFULL * LDW + j0 + jl;

    // per-lane packed X row pointers (n = nt*8 + g); buffers pre-padded with zeros
    const uint2* __restrict__ xbase = (LAYER == 0) ? g_x0 : (LAYER == 1) ? g_x1 : g_x2;
    const uint2* xr[3];
#pragma unroll
    for (int nt = 0; nt < 3; ++nt)
        xr[nt] = xbase + ((size_t)b * NPAD + nt * 8 + g) * KP;

    float fA[32];
    float d[2][3][4] = {};                 // [m-tile][n-tile][frag]

    auto pref = [&](int ch) {              // stage next A chunk into registers
        const int kc0 = kbase + ch * KCC;
#pragma unroll
        for (int pass = 0; pass < 8; ++pass) {
            const int krow = kc0 + (h + pass * 2) * 4;
#pragma unroll
            for (int u = 0; u < 4; ++u)
                fA[pass * 4 + u] = (LAYER != 0 || (krow + u) < D_IN)
                     ? __ldg(wcol + (size_t)(krow + u) * LDW) : 0.f;
        }
    };
    auto sts = [&]() {                     // convert + store staged A to smem
#pragma unroll
        for (int pass = 0; pass < 8; ++pass) {
            const int k0 = (h + pass * 2) * 4;
            const int si = jl * SP + (k0 >> 1);
            sAhi[si]     = hi_pair(fA[pass * 4 + 0], fA[pass * 4 + 1]);
            sAhi[si + 1] = hi_pair(fA[pass * 4 + 2], fA[pass * 4 + 3]);
            sAlo[si]     = lo_pair(fA[pass * 4 + 0], fA[pass * 4 + 1]);
            sAlo[si + 1] = lo_pair(fA[pass * 4 + 2], fA[pass * 4 + 3]);
        }
    };

    pref(0);
#pragma unroll 1
    for (int ch = 0; ch < NCH; ++ch) {
        sts();
        __syncthreads();
        if (ch + 1 < NCH) pref(ch + 1);    // next chunk's LDGs fly under the MMAs
        const int kc0 = kbase + ch * KCC + h * 32;
#pragma unroll
        for (int ks = 0; ks < 2; ++ks) {
            const int pi = ((kc0 + ks * 16) >> 1) + t;
            // ---- fragments: B direct from packed gmem, A from smem ----
            uint32_t bh[3][2], bl[3][2];
#pragma unroll
            for (int nt = 0; nt < 3; ++nt) {
                const uint2 v0 = __ldg(xr[nt] + pi);
                const uint2 v1 = __ldg(xr[nt] + pi + 4);
                bh[nt][0] = v0.x; bh[nt][1] = v1.x;
                bl[nt][0] = v0.y; bl[nt][1] = v1.y;
            }
            const int ci = h * 16 + ks * 8 + t;
            uint32_t ah[2][4], al[2][4];
#pragma unroll
            for (int mt = 0; mt < 2; ++mt) {
                const int ar0 = (jt * 32 + mt * 16 + g) * SP;
                const int ar1 = ar0 + 8 * SP;
                ah[mt][0] = sAhi[ar0 + ci];     ah[mt][1] = sAhi[ar1 + ci];
                ah[mt][2] = sAhi[ar0 + ci + 4]; ah[mt][3] = sAhi[ar1 + ci + 4];
                al[mt][0] = sAlo[ar0 + ci];     al[mt][1] = sAlo[ar1 + ci];
                al[mt][2] = sAlo[ar0 + ci + 4]; al[mt][3] = sAlo[ar1 + ci + 4];
            }
            // ---- term-major order: same-accumulator MMAs are 6 apart ----
#pragma unroll
            for (int mt = 0; mt < 2; ++mt)
#pragma unroll
                for (int nt = 0; nt < 3; ++nt) mma16816(d[mt][nt], ah[mt], bh[nt]);
#pragma unroll
            for (int mt = 0; mt < 2; ++mt)
#pragma unroll
                for (int nt = 0; nt < 3; ++nt) mma16816(d[mt][nt], ah[mt], bl[nt]);
#pragma unroll
            for (int mt = 0; mt < 2; ++mt)
#pragma unroll
                for (int nt = 0; nt < 3; ++nt) mma16816(d[mt][nt], al[mt], bh[nt]);
        }
        __syncthreads();
    }

    // ---- cross-half reduction through smem (reuse sAhi as float buffer) ----
    float* red = reinterpret_cast<float*>(sAhi);            // 128 lanes x 24 floats
    if (h == 1) {
#pragma unroll
        for (int mt = 0; mt < 2; ++mt)
#pragma unroll
            for (int nt = 0; nt < 3; ++nt)
#pragma unroll
                for (int i = 0; i < 4; ++i)
                    red[(jt * 32 + l) * 24 + mt * 12 + nt * 4 + i] = d[mt][nt][i];
    }
    __syncthreads();
    if (h == 0) {
#pragma unroll
        for (int mt = 0; mt < 2; ++mt)
#pragma unroll
            for (int nt = 0; nt < 3; ++nt)
#pragma unroll
                for (int i = 0; i < 4; ++i)
                    d[mt][nt][i] += red[(jt * 32 + l) * 24 + mt * 12 + nt * 4 + i];

        // ---- epilogue (h==0 warps only) ----
#pragma unroll
        for (int mt = 0; mt < 2; ++mt) {
            const int j1 = j0 + jt * 32 + mt * 16 + g;
            if (LAYER == 2) {
                float* __restrict__ outp = g_p + (((size_t)kb * BATCH + b) * ROWS) * D_OUT;
#pragma unroll
                for (int nt = 0; nt < 3; ++nt) {
                    const int n0 = nt * 8 + 2 * t;
                    if (n0 < ROWS) {
                        outp[(size_t)n0 * D_OUT + j1]     = d[mt][nt][0];
                        outp[(size_t)n0 * D_OUT + j1 + 8] = d[mt][nt][2];
                    }
                    if (n0 + 1 < ROWS) {
                        outp[(size_t)(n0 + 1) * D_OUT + j1]     = d[mt][nt][1];
                        outp[(size_t)(n0 + 1) * D_OUT + j1 + 8] = d[mt][nt][3];
                    }
                }
            } else {
                const float bv1 = __ldg(bias + (size_t)e * LDW + j1);
                const float bv2 = __ldg(bias + (size_t)e * LDW + j1 + 8);
                float* __restrict__ outp = ((LAYER == 0) ? g_h1 : g_h2) + ((size_t)b * ROWS) * LDW;
#pragma unroll
                for (int nt = 0; nt < 3; ++nt) {
                    const int n0 = nt * 8 + 2 * t;
                    if (n0 < ROWS) {
                        outp[(size_t)n0 * LDW + j1]     = fmaxf(d[mt][nt][0] + bv1, 0.f);
                        outp[(size_t)n0 * LDW + j1 + 8] = fmaxf(d[mt][nt][2] + bv2, 0.f);
                    }
                    if (n0 + 1 < ROWS) {
                        outp[(size_t)(n0 + 1) * LDW + j1]     = fmaxf(d[mt][nt][1] + bv1, 0.f);
                        outp[(size_t)(n0 + 1) * LDW + j1 + 8] = fmaxf(d[mt][nt][3] + bv2, 0.f);
                    }
                }
            }
        }
    }
}

// ---------------- reduce 4 L3 partials + b3 + relu + logits ----------------
__global__ void __launch_bounds__(256) logits_kernel(const int* __restrict__ tar,
                                                     const float* __restrict__ b3,
                                                     float* __restrict__ out) {
    __shared__ float sQK[ROWS * D_OUT];
    const int b = blockIdx.x;
    const int tid = threadIdx.x;
    const int e = tar[b];
    const size_t SL4 = ((size_t)BATCH * ROWS * D_OUT) / 4;
    const size_t base4 = ((size_t)b * ROWS * D_OUT) / 4;
    const float4* __restrict__ gp4 = (const float4*)g_p;
    const float4* __restrict__ b34 = (const float4*)(b3 + (size_t)e * D_OUT);
#pragma unroll 1
    for (int idx = tid; idx < (ROWS * D_OUT) / 4; idx += 256) {
        float4 bv = __ldg(b34 + (idx & 31));
        float4 a0 = gp4[base4 + idx];
        float4 a1 = gp4[SL4 + base4 + idx];
        float4 a2 = gp4[2 * SL4 + base4 + idx];
        float4 a3 = gp4[3 * SL4 + base4 + idx];
        float4 r;
        r.x = fmaxf(bv.x + a0.x + a1.x + a2.x + a3.x, 0.f);
        r.y = fmaxf(bv.y + a0.y + a1.y + a2.y + a3.y, 0.f);
        r.z = fmaxf(bv.z + a0.z + a1.z + a2.z + a3.z, 0.f);
        r.w = fmaxf(bv.w + a0.w + a1.w + a2.w + a3.w, 0.f);
        *reinterpret_cast<float4*>(&sQK[idx * 4]) = r;
    }
    __syncthreads();
    const int k = tid >> 4, l = tid & 15;
    float s = 0.f;
#pragma unroll
    for (int j = 0; j < D_OUT / 16; ++j) {
        const int col = l + j * 16;
        s += sQK[col] * sQK[(k + 1) * D_OUT + col];
    }
    s += __shfl_xor_sync(0xFFFFFFFFu, s, 1);
    s += __shfl_xor_sync(0xFFFFFFFFu, s, 2);
    s += __shfl_xor_sync(0xFFFFFFFFu, s, 4);
    s += __shfl_xor_sync(0xFFFFFFFFu, s, 8);
    if (l == 0) out[b * KSAMP + k] = s * INV_T;
}

// ---------------- launch ----------------
extern "C" void kernel_launch(void* const* d_in, const int* in_sizes, int n_in,
                              void* d_out, int out_size) {
    const float* v2s  = (const float*)d_in[0];
    const float* W1   = (const float*)d_in[1];
    const float* b1   = (const float*)d_in[2];
    const float* W2   = (const float*)d_in[3];
    const float* b2   = (const float*)d_in[4];
    const float* W3   = (const float*)d_in[5];
    const float* b3   = (const float*)d_in[6];
    const int*   tar  = (const int*)d_in[7];
    const int*   sidx = (const int*)d_in[8];
    float* out = (float*)d_out;

    pack_x0<<<BATCH, 256>>>(v2s, sidx);                                   // 1st
    gemm_kernel<0><<<BATCH * (H1 / 128), 256>>>(tar, W1, b1);             // 2nd
    pack_h<1><<<BATCH * NPAD, 256>>>();                                   // 3rd
    gemm_kernel<1><<<BATCH * (H2 / 128), 256>>>(tar, W2, b2);             // 4th (profiled)
    pack_h<2><<<BATCH * NPAD, 256>>>();                                   // 5th
    gemm_kernel<2><<<BATCH * 4, 256>>>(tar, W3, b3);                      // 6th
    logits_kernel<<<BATCH, 256>>>(tar, b3, out);                           // 7th
}

// round 17
// speedup vs baseline: 1.1549x; 1.1549x over previous
#include <cuda_runtime.h>
#include <cuda_bf16.h>
#include <cstdint>

// ---------------- problem constants ----------------
#define BATCH 32
#define KSAMP 16
#define D_IN  312
#define H1    1024
#define H2    2048
#define D_OUT 128
#define ROWS  17
#define NPAD  24
#define INV_T 8.3333333333333333f
#define KCC   64            // K per chunk
#define ROWF  132           // smem floats per A row (128 + 4 pad -> conflict-free frags)
#define ABUF  (KCC * ROWF)  // 8448 floats per stage
#define KP0   160           // packed X pair-stride per row
#define KP1   512
#define KP2   1024
#define SMEM_BYTES (2 * ABUF * 4)   // 67584

// ---------------- scratch (referenced ONLY from device code) ----------------
__device__ float g_h1[(size_t)BATCH * ROWS * H1];
__device__ float g_h2[(size_t)BATCH * ROWS * H2];
__device__ float g_p [(size_t)4 * BATCH * ROWS * D_OUT];
__device__ uint2 g_x0[(size_t)BATCH * NPAD * KP0];
__device__ uint2 g_x1[(size_t)BATCH * NPAD * KP1];
__device__ uint2 g_x2[(size_t)BATCH * NPAD * KP2];

// ---------------- bf16 hi/lo pair packing ----------------
__device__ __forceinline__ uint32_t hi_pair(float f0, float f1) {
    return __byte_perm(__float_as_uint(f0), __float_as_uint(f1), 0x7632);
}
__device__ __forceinline__ uint32_t lo_pair(float f0, float f1) {
    float l0 = f0 - __uint_as_float(__float_as_uint(f0) & 0xFFFF0000u);
    float l1 = f1 - __uint_as_float(__float_as_uint(f1) & 0xFFFF0000u);
    __nv_bfloat162 p = __floats2bfloat162_rn(l0, l1);
    return reinterpret_cast<uint32_t&>(p);
}

// ---------------- mma.sync m16n8k16 bf16 ----------------
__device__ __forceinline__ void mma16816(float d[4], const uint32_t a[4], const uint32_t b[2]) {
    asm volatile(
        "mma.sync.aligned.m16n8k16.row.col.f32.bf16.bf16.f32 "
        "{%0,%1,%2,%3}, {%4,%5,%6,%7}, {%8,%9}, {%0,%1,%2,%3};"
        : "+f"(d[0]), "+f"(d[1]), "+f"(d[2]), "+f"(d[3])
        : "r"(a[0]), "r"(a[1]), "r"(a[2]), "r"(a[3]), "r"(b[0]), "r"(b[1]));
}

// ---------------- cp.async helpers ----------------
__device__ __forceinline__ void cp_async16(uint32_t dst, const void* src, int src_bytes) {
    asm volatile("cp.async.cg.shared.global [%0], [%1], 16, %2;"
                 :: "r"(dst), "l"(src), "r"(src_bytes));
}
#define CP_COMMIT() asm volatile("cp.async.commit_group;" ::: "memory")

// ---------------- pack kernels ----------------
__global__ void __launch_bounds__(256) pack_x0(const float* __restrict__ v2s,
                                               const int* __restrict__ sidx) {
    const int b = blockIdx.x;
    __shared__ int sRow[NPAD];
    if (threadIdx.x < NPAD)
        sRow[threadIdx.x] = (threadIdx.x == 0) ? b
                          : (threadIdx.x < ROWS ? sidx[b * KSAMP + threadIdx.x - 1] : -1);
    __syncthreads();
    for (int i = threadIdx.x; i < NPAD * KP0; i += 256) {
        const int n = i / KP0, p = i - n * KP0;
        const int r = sRow[n];
        float f0 = 0.f, f1 = 0.f;
        if (r >= 0 && 2 * p + 1 < D_IN) {
            f0 = v2s[(size_t)r * D_IN + 2 * p];
            f1 = v2s[(size_t)r * D_IN + 2 * p + 1];
        }
        g_x0[(size_t)b * NPAD * KP0 + i] = make_uint2(hi_pair(f0, f1), lo_pair(f0, f1));
    }
}

template<int LAYER>
__global__ void __launch_bounds__(256) pack_h() {
    constexpr int H = (LAYER == 1) ? H1 : H2;
    const float* __restrict__ src = (LAYER == 1) ? g_h1 : g_h2;
    uint2* __restrict__ dst = (LAYER == 1) ? g_x1 : g_x2;
    const int bn = blockIdx.x;
    const int b = bn / NPAD, n = bn - b * NPAD;
    const bool ok = (n < ROWS);
    const float2* __restrict__ s = reinterpret_cast<const float2*>(
        src + ((size_t)b * ROWS + (ok ? n : 0)) * H);
    uint2* __restrict__ d = dst + (size_t)bn * (H / 2);
    for (int p = threadIdx.x; p < H / 2; p += 256) {
        float2 f = ok ? s[p] : make_float2(0.f, 0.f);
        d[p] = make_uint2(hi_pair(f.x, f.y), lo_pair(f.x, f.y));
    }
}

// ---------------- GEMM: cp.async A pipeline, inline conversion ----------------
template<int LAYER>
__global__ void __launch_bounds__(256, 2) gemm_kernel(const int* __restrict__ tar,
                                                      const float* __restrict__ W,
                                                      const float* __restrict__ bias) {
    constexpr int LDW   = (LAYER == 0) ? H1 : (LAYER == 1) ? H2 : D_OUT;
    constexpr int KFULL = (LAYER == 0) ? D_IN : (LAYER == 1) ? H1 : H2;
    constexpr int KBLK  = (LAYER == 2) ? 512 : KFULL;
    constexpr int NCH   = (KBLK + KCC - 1) / KCC;            // 5 / 16 / 8
    constexpr int JB    = LDW / 128;
    constexpr int KP    = (LAYER == 0) ? KP0 : (LAYER == 1) ? KP1 : KP2;

    extern __shared__ __align__(16) float sA[];              // 2 stages x [64][132] fp32

    const int tid = threadIdx.x;
    int b, jb, kb;
    if (LAYER == 2) { b = blockIdx.x >> 2; kb = blockIdx.x & 3; jb = 0; }
    else            { b = blockIdx.x / JB; jb = blockIdx.x % JB; kb = 0; }
    const int e = tar[b];
    const int kbase = (LAYER == 2) ? kb * 512 : 0;
    const int j0 = jb * 128;

    const int w = tid >> 5, l = tid & 31;
    const int g = l >> 2, t = l & 3;
    const int jt = w & 3;                  // j-tile (m32)
    const int h  = w >> 2;                 // k-half (k32)

    const uint32_t sbase = (uint32_t)__cvta_generic_to_shared(sA);

    // per-lane packed X row pointers (n = nt*8 + g)
    const uint2* __restrict__ xbase = (LAYER == 0) ? g_x0 : (LAYER == 1) ? g_x1 : g_x2;
    const uint2* xr[3];
#pragma unroll
    for (int nt = 0; nt < 3; ++nt)
        xr[nt] = xbase + ((size_t)b * NPAD + nt * 8 + g) * KP;

    float d[2][3][4] = {};

    // fill A chunk ch into stage (ch&1): 8 passes, warp w = row r within pass
    auto fill = [&](int ch) {
        const int kc0 = kbase + ch * KCC;
        const uint32_t sdst = sbase + (uint32_t)((ch & 1) * ABUF * 4);
        const int c4 = (tid & 31) * 4;
#pragma unroll
        for (int p = 0; p < 8; ++p) {
            const int r = (tid >> 5) + p * 8;
            const int krow = kc0 + r;
            const int krc = (LAYER == 0 && krow >= KFULL) ? (KFULL - 1) : krow;
            const float* src = W + ((size_t)e * KFULL + krc) * LDW + j0 + c4;
            const int nb = (LAYER != 0 || krow < KFULL) ? 16 : 0;
            cp_async16(sdst + (uint32_t)((r * ROWF + c4) * 4), src, nb);
        }
        CP_COMMIT();
    };

    fill(0);
    fill(1);                                   // NCH >= 5 always

#pragma unroll 1
    for (int ch = 0; ch < NCH; ++ch) {
        // B fragments for both k16-steps of this warp's half (independent of smem)
        uint2 v[2][3][2];
#pragma unroll
        for (int ks = 0; ks < 2; ++ks) {
            const int pi = ((kbase + ch * KCC + h * 32 + ks * 16) >> 1) + t;
#pragma unroll
            for (int nt = 0; nt < 3; ++nt) {
                v[ks][nt][0] = __ldg(xr[nt] + pi);
                v[ks][nt][1] = __ldg(xr[nt] + pi + 4);
            }
        }
        if (ch < NCH - 1) asm volatile("cp.async.wait_group 1;" ::: "memory");
        else              asm volatile("cp.async.wait_group 0;" ::: "memory");
        __syncthreads();

        const float* abuf = sA + (ch & 1) * ABUF + (h * 32) * ROWF + jt * 32;
#pragma unroll
        for (int ks = 0; ks < 2; ++ks) {
            const float* apk = abuf + ks * 16 * ROWF;
            uint32_t bh[3][2], bl[3][2];
#pragma unroll
            for (int nt = 0; nt < 3; ++nt) {
                bh[nt][0] = v[ks][nt][0].x; bh[nt][1] = v[ks][nt][1].x;
                bl[nt][0] = v[ks][nt][0].y; bl[nt][1] = v[ks][nt][1].y;
            }
#pragma unroll
            for (int mt = 0; mt < 2; ++mt) {
                const float* ap = apk + mt * 16;
                const float f00 = ap[(2*t)*ROWF + g],       f01 = ap[(2*t+1)*ROWF + g];
                const float f10 = ap[(2*t)*ROWF + g + 8],   f11 = ap[(2*t+1)*ROWF + g + 8];
                const float f20 = ap[(2*t+8)*ROWF + g],     f21 = ap[(2*t+9)*ROWF + g];
                const float f30 = ap[(2*t+8)*ROWF + g + 8], f31 = ap[(2*t+9)*ROWF + g + 8];
                uint32_t ah[4] = {hi_pair(f00,f01), hi_pair(f10,f11),
                                  hi_pair(f20,f21), hi_pair(f30,f31)};
                uint32_t al[4] = {lo_pair(f00,f01), lo_pair(f10,f11),
                                  lo_pair(f20,f21), lo_pair(f30,f31)};
#pragma unroll
                for (int nt = 0; nt < 3; ++nt) mma16816(d[mt][nt], ah, bh[nt]);
#pragma unroll
                for (int nt = 0; nt < 3; ++nt) mma16816(d[mt][nt], ah, bl[nt]);
#pragma unroll
                for (int nt = 0; nt < 3; ++nt) mma16816(d[mt][nt], al, bh[nt]);
            }
        }
        __syncthreads();
        if (ch + 2 < NCH) fill(ch + 2);
    }

    // ---- cross-half reduction through smem (reuse sA) ----
    float* red = sA;                        // 128 lanes x 24 floats <= ABUF
    if (h == 1) {
#pragma unroll
        for (int mt = 0; mt < 2; ++mt)
#pragma unroll
            for (int nt = 0; nt < 3; ++nt)
#pragma unroll
                for (int i = 0; i < 4; ++i)
                    red[(jt * 32 + l) * 24 + mt * 12 + nt * 4 + i] = d[mt][nt][i];
    }
    __syncthreads();
    if (h == 0) {
#pragma unroll
        for (int mt = 0; mt < 2; ++mt)
#pragma unroll
            for (int nt = 0; nt < 3; ++nt)
#pragma unroll
                for (int i = 0; i < 4; ++i)
                    d[mt][nt][i] += red[(jt * 32 + l) * 24 + mt * 12 + nt * 4 + i];

#pragma unroll
        for (int mt = 0; mt < 2; ++mt) {
            const int j1 = j0 + jt * 32 + mt * 16 + g;
            if (LAYER == 2) {
                float* __restrict__ outp = g_p + (((size_t)kb * BATCH + b) * ROWS) * D_OUT;
#pragma unroll
                for (int nt = 0; nt < 3; ++nt) {
                    const int n0 = nt * 8 + 2 * t;
                    if (n0 < ROWS) {
                        outp[(size_t)n0 * D_OUT + j1]     = d[mt][nt][0];
                        outp[(size_t)n0 * D_OUT + j1 + 8] = d[mt][nt][2];
                    }
                    if (n0 + 1 < ROWS) {
                        outp[(size_t)(n0 + 1) * D_OUT + j1]     = d[mt][nt][1];
                        outp[(size_t)(n0 + 1) * D_OUT + j1 + 8] = d[mt][nt][3];
                    }
                }
            } else {
                const float bv1 = __ldg(bias + (size_t)e * LDW + j1);
                const float bv2 = __ldg(bias + (size_t)e * LDW + j1 + 8);
                float* __restrict__ outp = ((LAYER == 0) ? g_h1 : g_h2) + ((size_t)b * ROWS) * LDW;
#pragma unroll
                for (int nt = 0; nt < 3; ++nt) {
                    const int n0 = nt * 8 + 2 * t;
                    if (n0 < ROWS) {
                        outp[(size_t)n0 * LDW + j1]     = fmaxf(d[mt][nt][0] + bv1, 0.f);
                        outp[(size_t)n0 * LDW + j1 + 8] = fmaxf(d[mt][nt][2] + bv2, 0.f);
                    }
                    if (n0 + 1 < ROWS) {
                        outp[(size_t)(n0 + 1) * LDW + j1]     = fmaxf(d[mt][nt][1] + bv1, 0.f);
                        outp[(size_t)(n0 + 1) * LDW + j1 + 8] = fmaxf(d[mt][nt][3] + bv2, 0.f);
                    }
                }
            }
        }
    }
}

// ---------------- reduce 4 L3 partials + b3 + relu + logits ----------------
__global__ void __launch_bounds__(256) logits_kernel(const int* __restrict__ tar,
                                                     const float* __restrict__ b3,
                                                     float* __restrict__ out) {
    __shared__ float sQK[ROWS * D_OUT];
    const int b = blockIdx.x;
    const int tid = threadIdx.x;
    const int e = tar[b];
    const size_t SL4 = ((size_t)BATCH * ROWS * D_OUT) / 4;
    const size_t base4 = ((size_t)b * ROWS * D_OUT) / 4;
    const float4* __restrict__ gp4 = (const float4*)g_p;
    const float4* __restrict__ b34 = (const float4*)(b3 + (size_t)e * D_OUT);
#pragma unroll 1
    for (int idx = tid; idx < (ROWS * D_OUT) / 4; idx += 256) {
        float4 bv = __ldg(b34 + (idx & 31));
        float4 a0 = gp4[base4 + idx];
        float4 a1 = gp4[SL4 + base4 + idx];
        float4 a2 = gp4[2 * SL4 + base4 + idx];
        float4 a3 = gp4[3 * SL4 + base4 + idx];
        float4 r;
        r.x = fmaxf(bv.x + a0.x + a1.x + a2.x + a3.x, 0.f);
        r.y = fmaxf(bv.y + a0.y + a1.y + a2.y + a3.y, 0.f);
        r.z = fmaxf(bv.z + a0.z + a1.z + a2.z + a3.z, 0.f);
        r.w = fmaxf(bv.w + a0.w + a1.w + a2.w + a3.w, 0.f);
        *reinterpret_cast<float4*>(&sQK[idx * 4]) = r;
    }
    __syncthreads();
    const int k = tid >> 4, l = tid & 15;
    float s = 0.f;
#pragma unroll
    for (int j = 0; j < D_OUT / 16; ++j) {
        const int col = l + j * 16;
        s += sQK[col] * sQK[(k + 1) * D_OUT + col];
    }
    s += __shfl_xor_sync(0xFFFFFFFFu, s, 1);
    s += __shfl_xor_sync(0xFFFFFFFFu, s, 2);
    s += __shfl_xor_sync(0xFFFFFFFFu, s, 4);
    s += __shfl_xor_sync(0xFFFFFFFFu, s, 8);
    if (l == 0) out[b * KSAMP + k] = s * INV_T;
}

// ---------------- launch ----------------
extern "C" void kernel_launch(void* const* d_in, const int* in_sizes, int n_in,
                              void* d_out, int out_size) {
    const float* v2s  = (const float*)d_in[0];
    const float* W1   = (const float*)d_in[1];
    const float* b1   = (const float*)d_in[2];
    const float* W2   = (const float*)d_in[3];
    const float* b2   = (const float*)d_in[4];
    const float* W3   = (const float*)d_in[5];
    const float* b3   = (const float*)d_in[6];
    const int*   tar  = (const int*)d_in[7];
    const int*   sidx = (const int*)d_in[8];
    float* out = (float*)d_out;

    cudaFuncSetAttribute(gemm_kernel<0>, cudaFuncAttributeMaxDynamicSharedMemorySize, SMEM_BYTES);
    cudaFuncSetAttribute(gemm_kernel<1>, cudaFuncAttributeMaxDynamicSharedMemorySize, SMEM_BYTES);
    cudaFuncSetAttribute(gemm_kernel<2>, cudaFuncAttributeMaxDynamicSharedMemorySize, SMEM_BYTES);

    pack_x0<<<BATCH, 256>>>(v2s, sidx);                                           // 1st
    gemm_kernel<0><<<BATCH * (H1 / 128), 256, SMEM_BYTES>>>(tar, W1, b1);         // 2nd
    pack_h<1><<<BATCH * NPAD, 256>>>();                                           // 3rd
    gemm_kernel<1><<<BATCH * (H2 / 128), 256, SMEM_BYTES>>>(tar, W2, b2);         // 4th (profiled)
    pack_h<2><<<BATCH * NPAD, 256>>>();                                           // 5th
    gemm_kernel<2><<<BATCH * 4, 256, SMEM_BYTES>>>(tar, W3, b3);                  // 6th
    logits_kernel<<<BATCH, 256>>>(tar, b3, out);                                   // 7th
}